// round 1
// baseline (speedup 1.0000x reference)
#include <cuda_runtime.h>
#include <cuda_bf16.h>
#include <cstdint>

#define Bq 4
#define NF 5
#define HSq 512
#define Sq 1024

// x index helper within one batch: face ff, row jj, col ii
#define XF(ff,jj,ii) xb[((size_t)(ff)*HSq + (jj))*Sq + (ii)]

__global__ void __launch_bounds__(256) inner_kernel(
    const float* __restrict__ x,
    const float* __restrict__ wi,
    float* __restrict__ out)
{
    int i = 1 + blockIdx.x * blockDim.x + threadIdx.x;
    if (i > Sq - 2) return;
    int j  = 1 + blockIdx.y;
    int bf = blockIdx.z;                // b*NF + f
    int b  = bf / NF;
    int f  = bf - b * NF;

    const float* __restrict__ xp = x + (size_t)bf * HSq * Sq;

    float ctr = xp[(size_t)j * Sq + i];

    const int WP = (HSq - 2) * (Sq - 2);
    int k = (j - 1) * (Sq - 2) + (i - 1);
    float w0 = wi[k];
    float w1 = wi[k +     WP];
    float w2 = wi[k + 2 * WP];
    float w3 = wi[k + 3 * WP];
    float w4 = wi[k + 4 * WP];
    float w5 = wi[k + 5 * WP];

    float c0 = (xp[(size_t)(j - 1) * Sq + (i - 1)] - ctr) * w0;
    float c1 = (xp[(size_t)(j + 1) * Sq + (i + 1)] - ctr) * w1;
    float c2 = (xp[(size_t)(j - 1) * Sq + i      ] - ctr) * w2
             + (xp[(size_t)j       * Sq + (i + 1)] - ctr) * w3;
    float c3 = (xp[(size_t)j       * Sq + (i - 1)] - ctr) * w4
             + (xp[(size_t)(j + 1) * Sq + i      ] - ctr) * w5;

    const size_t CP = (size_t)NF * HSq * Sq;
    size_t ob = ((((size_t)b * 4) * NF + f) * HSq + j) * Sq + i;
    out[ob]          = c0;
    out[ob +     CP] = c1;
    out[ob + 2 * CP] = c2;
    out[ob + 3 * CP] = c3;
}

__global__ void __launch_bounds__(256) boundary_kernel(
    const float* __restrict__ x,
    const float* __restrict__ poles,
    const float* __restrict__ we,    // w_east  (6, HS-1)
    const float* __restrict__ wcn,   // (5,)
    const float* __restrict__ wne,   // (6, HS-2)
    const float* __restrict__ wnne,  // (6,)
    const float* __restrict__ wnw,   // (6, HS-2)
    const float* __restrict__ wnww,  // (6,)
    const float* __restrict__ wwe,   // w_west (6, HS-1)
    const float* __restrict__ wsw,   // (6, HS-1)
    const float* __restrict__ wsse,  // (5,)
    const float* __restrict__ wse,   // (6, HS-2)
    const float* __restrict__ wcs,   // (5,)
    float* __restrict__ out)
{
    const int PER = 2 * Sq + 2 * (HSq - 2);       // 3068 perimeter points per (b,f)
    int tid = blockIdx.x * blockDim.x + threadIdx.x;
    if (tid >= Bq * NF * PER) return;

    int bf = tid / PER;
    int p  = tid - bf * PER;
    int b  = bf / NF;
    int f  = bf - b * NF;
    int pf  = (f == 0) ? 4 : f - 1;   // prev face
    int nf2 = (f == 4) ? 0 : f + 1;   // next face

    const float* __restrict__ xb = x + (size_t)b * NF * HSq * Sq;

    float c0, c1, c2, c3;
    int j, i;

    if (p < Sq) {
        // ---- top row j = 0 ----
        j = 0; i = p;
        float ctr = XF(f, 0, i);
        if (i == 0) {
            // di (corner 0,0), wcs
            c0 = (XF(pf, HSq - 1, HSq - 1) - ctr) * wcs[0];
            c1 = (XF(f, 1, 1) - ctr) * wcs[1];
            c2 = (XF(pf, HSq - 1, HSq) - ctr) * wcs[2] + (XF(f, 0, 1) - ctr) * wcs[3];
            c3 = (XF(f, 1, 0) - ctr) * wcs[4];
        } else if (i <= HSq - 1) {
            // ei, w_east, k = i-1, width HS-1
            int k = i - 1; const int W = HSq - 1;
            c0 = (XF(pf, HSq - 1, HSq + k) - ctr) * we[k];
            c1 = (XF(f, 1, i + 1) - ctr) * we[W + k];
            c2 = (XF(pf, HSq - 1, HSq + 1 + k) - ctr) * we[2 * W + k]
               + (XF(f, 0, i + 1) - ctr) * we[3 * W + k];
            c3 = (XF(f, 0, i - 1) - ctr) * we[4 * W + k]
               + (XF(f, 1, i) - ctr) * we[5 * W + k];
        } else if (i == HSq) {
            // ci, wcn
            c0 = (XF(pf, HSq - 1, Sq - 1) - ctr) * wcn[0];
            c1 = (XF(f, 1, HSq + 1) - ctr) * wcn[1];
            c2 = (XF(f, 0, HSq + 1) - ctr) * wcn[2];
            c3 = (XF(f, 0, HSq - 1) - ctr) * wcn[3] + (XF(f, 1, HSq) - ctr) * wcn[4];
        } else if (i <= Sq - 2) {
            // ni, w_ne, k = i-(HS+1), width HS-2
            int k = i - (HSq + 1); const int W = HSq - 2;
            c0 = (XF(pf, HSq - 2 - k, Sq - 1) - ctr) * wne[k]
               + (XF(pf, HSq - 1 - k, Sq - 1) - ctr) * wne[W + k];
            c1 = (XF(f, 1, i + 1) - ctr) * wne[2 * W + k]
               + (XF(f, 1, i) - ctr) * wne[3 * W + k];
            c2 = (XF(f, 0, i + 1) - ctr) * wne[4 * W + k];
            c3 = (XF(f, 0, i - 1) - ctr) * wne[5 * W + k];
        } else {
            // qi (corner 0, S-1), wnne
            c0 = (XF(pf, 0, Sq - 1) - ctr) * wnne[0] + (XF(pf, 1, Sq - 1) - ctr) * wnne[1];
            c1 = (XF(nf2, 0, Sq - 1) - ctr) * wnne[2] + (XF(f, 1, Sq - 1) - ctr) * wnne[3];
            c2 = (poles[b * 2 + 1] - ctr) * wnne[4];
            c3 = (XF(f, 0, Sq - 2) - ctr) * wnne[5];
        }
    } else if (p < 2 * Sq) {
        // ---- bottom row j = HS-1 ----
        j = HSq - 1; i = p - Sq;
        float ctr = XF(f, HSq - 1, i);
        if (i == 0) {
            // pi, wsse
            c0 = (XF(pf, HSq - 1, 0) - ctr) * wsse[0];
            c1 = (XF(nf2, HSq - 1, 0) - ctr) * wsse[1];
            c2 = (XF(f, HSq - 2, 0) - ctr) * wsse[2] + (XF(f, HSq - 1, 1) - ctr) * wsse[3];
            c3 = (poles[b * 2 + 0] - ctr) * wsse[4];
        } else if (i <= HSq - 1) {
            // si, w_sw, k = i-1, width HS-1
            int k = i - 1; const int W = HSq - 1;
            c0 = (XF(f, HSq - 2, i - 1) - ctr) * wsw[k];
            c1 = (XF(nf2, HSq - 2 - k, 0) - ctr) * wsw[W + k];
            c2 = (XF(f, HSq - 2, i) - ctr) * wsw[2 * W + k]
               + (XF(f, HSq - 1, i + 1) - ctr) * wsw[3 * W + k];
            c3 = (XF(f, HSq - 1, i - 1) - ctr) * wsw[4 * W + k]
               + (XF(nf2, HSq - 1 - k, 0) - ctr) * wsw[5 * W + k];
        } else if (i <= Sq - 2) {
            // ui, w_west, k = i-HS, width HS-1
            int k = i - HSq; const int W = HSq - 1;
            c0 = (XF(f, HSq - 2, i - 1) - ctr) * wwe[k];
            c1 = (XF(nf2, 0, 1 + k) - ctr) * wwe[W + k];
            c2 = (XF(f, HSq - 2, i) - ctr) * wwe[2 * W + k]
               + (XF(f, HSq - 1, i + 1) - ctr) * wwe[3 * W + k];
            c3 = (XF(f, HSq - 1, i - 1) - ctr) * wwe[4 * W + k]
               + (XF(nf2, 0, k) - ctr) * wwe[5 * W + k];
        } else {
            // gi (corner HS-1, S-1), wnww
            c0 = (XF(f, HSq - 2, Sq - 2) - ctr) * wnww[0];
            c1 = (XF(nf2, 0, HSq) - ctr) * wnww[1];
            c2 = (XF(f, HSq - 2, Sq - 1) - ctr) * wnww[2]
               + (XF(nf2, 0, HSq + 1) - ctr) * wnww[3];
            c3 = (XF(f, HSq - 1, Sq - 2) - ctr) * wnww[4]
               + (XF(nf2, 0, HSq - 1) - ctr) * wnww[5];
        }
    } else if (p < 2 * Sq + (HSq - 2)) {
        // ---- left column ri: j in [1, HS-2], i = 0 ----
        int k = p - 2 * Sq; j = 1 + k; i = 0;
        float ctr = XF(f, j, 0);
        const int W = HSq - 2;
        c0 = (XF(pf, HSq - 1, HSq - 1 - k) - ctr) * wse[k]
           + (XF(pf, HSq - 1, HSq - 2 - k) - ctr) * wse[W + k];
        c1 = (XF(f, j, 1) - ctr) * wse[2 * W + k]
           + (XF(f, j + 1, 1) - ctr) * wse[3 * W + k];
        c2 = (XF(f, j - 1, 0) - ctr) * wse[4 * W + k];
        c3 = (XF(f, j + 1, 0) - ctr) * wse[5 * W + k];
    } else {
        // ---- right column vi: j in [1, HS-2], i = S-1 ----
        int k = p - 2 * Sq - (HSq - 2); j = 1 + k; i = Sq - 1;
        float ctr = XF(f, j, Sq - 1);
        const int W = HSq - 2;
        c0 = (XF(f, j - 1, Sq - 2) - ctr) * wnw[k];
        c1 = (XF(nf2, 0, Sq - 2 - k) - ctr) * wnw[W + k];
        c2 = (XF(f, j - 1, Sq - 1) - ctr) * wnw[2 * W + k]
           + (XF(nf2, 0, Sq - 1 - k) - ctr) * wnw[3 * W + k];
        c3 = (XF(f, j, Sq - 2) - ctr) * wnw[4 * W + k]
           + (XF(f, j + 1, Sq - 1) - ctr) * wnw[5 * W + k];
    }

    const size_t CP = (size_t)NF * HSq * Sq;
    size_t ob = ((((size_t)b * 4) * NF + f) * HSq + j) * Sq + i;
    out[ob]          = c0;
    out[ob +     CP] = c1;
    out[ob + 2 * CP] = c2;
    out[ob + 3 * CP] = c3;
}

extern "C" void kernel_launch(void* const* d_in, const int* in_sizes, int n_in,
                              void* d_out, int out_size)
{
    const float* x     = (const float*)d_in[0];
    const float* poles = (const float*)d_in[1];
    const float* wi    = (const float*)d_in[2];   // w_inner
    const float* we    = (const float*)d_in[3];   // w_east
    const float* wcn   = (const float*)d_in[4];
    const float* wne   = (const float*)d_in[5];
    const float* wnne  = (const float*)d_in[6];
    const float* wnw   = (const float*)d_in[7];
    const float* wnww  = (const float*)d_in[8];
    const float* wwe   = (const float*)d_in[9];   // w_west
    const float* wsw   = (const float*)d_in[10];
    const float* wsse  = (const float*)d_in[11];
    const float* wse   = (const float*)d_in[12];
    const float* wcs   = (const float*)d_in[13];
    float* out = (float*)d_out;

    // Inner region: j in [1, HS-2], i in [1, S-2]
    dim3 block(256, 1, 1);
    dim3 grid((Sq - 2 + 255) / 256, HSq - 2, Bq * NF);
    inner_kernel<<<grid, block>>>(x, wi, out);

    // Perimeter
    const int PER = 2 * Sq + 2 * (HSq - 2);
    int total = Bq * NF * PER;
    boundary_kernel<<<(total + 255) / 256, 256>>>(
        x, poles, we, wcn, wne, wnne, wnw, wnww, wwe, wsw, wsse, wse, wcs, out);
}

// round 2
// speedup vs baseline: 1.0788x; 1.0788x over previous
#include <cuda_runtime.h>
#include <cuda_bf16.h>
#include <cstdint>

#define Bq 4
#define NF 5
#define HSq 512
#define Sq 1024

#define XF(ff,jj,ii) xb[((size_t)(ff)*HSq + (jj))*Sq + (ii)]

// Boundary point: ports the reference's 12 perimeter cases for one (j,i).
__device__ __forceinline__ void bpoint(
    const float* __restrict__ xb, const float* __restrict__ poles,
    const float* __restrict__ we,   const float* __restrict__ wcn,
    const float* __restrict__ wne,  const float* __restrict__ wnne,
    const float* __restrict__ wnw,  const float* __restrict__ wnww,
    const float* __restrict__ wwe,  const float* __restrict__ wsw,
    const float* __restrict__ wsse, const float* __restrict__ wse,
    const float* __restrict__ wcs,
    int b, int f, int pf, int nf2, int j, int i,
    float& c0, float& c1, float& c2, float& c3)
{
    if (j == 0) {
        float ctr = XF(f, 0, i);
        if (i == 0) {
            c0 = (XF(pf, HSq - 1, HSq - 1) - ctr) * wcs[0];
            c1 = (XF(f, 1, 1) - ctr) * wcs[1];
            c2 = (XF(pf, HSq - 1, HSq) - ctr) * wcs[2] + (XF(f, 0, 1) - ctr) * wcs[3];
            c3 = (XF(f, 1, 0) - ctr) * wcs[4];
        } else if (i <= HSq - 1) {
            int k = i - 1; const int W = HSq - 1;
            c0 = (XF(pf, HSq - 1, HSq + k) - ctr) * we[k];
            c1 = (XF(f, 1, i + 1) - ctr) * we[W + k];
            c2 = (XF(pf, HSq - 1, HSq + 1 + k) - ctr) * we[2 * W + k]
               + (XF(f, 0, i + 1) - ctr) * we[3 * W + k];
            c3 = (XF(f, 0, i - 1) - ctr) * we[4 * W + k]
               + (XF(f, 1, i) - ctr) * we[5 * W + k];
        } else if (i == HSq) {
            c0 = (XF(pf, HSq - 1, Sq - 1) - ctr) * wcn[0];
            c1 = (XF(f, 1, HSq + 1) - ctr) * wcn[1];
            c2 = (XF(f, 0, HSq + 1) - ctr) * wcn[2];
            c3 = (XF(f, 0, HSq - 1) - ctr) * wcn[3] + (XF(f, 1, HSq) - ctr) * wcn[4];
        } else if (i <= Sq - 2) {
            int k = i - (HSq + 1); const int W = HSq - 2;
            c0 = (XF(pf, HSq - 2 - k, Sq - 1) - ctr) * wne[k]
               + (XF(pf, HSq - 1 - k, Sq - 1) - ctr) * wne[W + k];
            c1 = (XF(f, 1, i + 1) - ctr) * wne[2 * W + k]
               + (XF(f, 1, i) - ctr) * wne[3 * W + k];
            c2 = (XF(f, 0, i + 1) - ctr) * wne[4 * W + k];
            c3 = (XF(f, 0, i - 1) - ctr) * wne[5 * W + k];
        } else {
            c0 = (XF(pf, 0, Sq - 1) - ctr) * wnne[0] + (XF(pf, 1, Sq - 1) - ctr) * wnne[1];
            c1 = (XF(nf2, 0, Sq - 1) - ctr) * wnne[2] + (XF(f, 1, Sq - 1) - ctr) * wnne[3];
            c2 = (poles[b * 2 + 1] - ctr) * wnne[4];
            c3 = (XF(f, 0, Sq - 2) - ctr) * wnne[5];
        }
    } else if (j == HSq - 1) {
        float ctr = XF(f, HSq - 1, i);
        if (i == 0) {
            c0 = (XF(pf, HSq - 1, 0) - ctr) * wsse[0];
            c1 = (XF(nf2, HSq - 1, 0) - ctr) * wsse[1];
            c2 = (XF(f, HSq - 2, 0) - ctr) * wsse[2] + (XF(f, HSq - 1, 1) - ctr) * wsse[3];
            c3 = (poles[b * 2 + 0] - ctr) * wsse[4];
        } else if (i <= HSq - 1) {
            int k = i - 1; const int W = HSq - 1;
            c0 = (XF(f, HSq - 2, i - 1) - ctr) * wsw[k];
            c1 = (XF(nf2, HSq - 2 - k, 0) - ctr) * wsw[W + k];
            c2 = (XF(f, HSq - 2, i) - ctr) * wsw[2 * W + k]
               + (XF(f, HSq - 1, i + 1) - ctr) * wsw[3 * W + k];
            c3 = (XF(f, HSq - 1, i - 1) - ctr) * wsw[4 * W + k]
               + (XF(nf2, HSq - 1 - k, 0) - ctr) * wsw[5 * W + k];
        } else if (i <= Sq - 2) {
            int k = i - HSq; const int W = HSq - 1;
            c0 = (XF(f, HSq - 2, i - 1) - ctr) * wwe[k];
            c1 = (XF(nf2, 0, 1 + k) - ctr) * wwe[W + k];
            c2 = (XF(f, HSq - 2, i) - ctr) * wwe[2 * W + k]
               + (XF(f, HSq - 1, i + 1) - ctr) * wwe[3 * W + k];
            c3 = (XF(f, HSq - 1, i - 1) - ctr) * wwe[4 * W + k]
               + (XF(nf2, 0, k) - ctr) * wwe[5 * W + k];
        } else {
            c0 = (XF(f, HSq - 2, Sq - 2) - ctr) * wnww[0];
            c1 = (XF(nf2, 0, HSq) - ctr) * wnww[1];
            c2 = (XF(f, HSq - 2, Sq - 1) - ctr) * wnww[2]
               + (XF(nf2, 0, HSq + 1) - ctr) * wnww[3];
            c3 = (XF(f, HSq - 1, Sq - 2) - ctr) * wnww[4]
               + (XF(nf2, 0, HSq - 1) - ctr) * wnww[5];
        }
    } else if (i == 0) {
        int k = j - 1; const int W = HSq - 2;
        float ctr = XF(f, j, 0);
        c0 = (XF(pf, HSq - 1, HSq - 1 - k) - ctr) * wse[k]
           + (XF(pf, HSq - 1, HSq - 2 - k) - ctr) * wse[W + k];
        c1 = (XF(f, j, 1) - ctr) * wse[2 * W + k]
           + (XF(f, j + 1, 1) - ctr) * wse[3 * W + k];
        c2 = (XF(f, j - 1, 0) - ctr) * wse[4 * W + k];
        c3 = (XF(f, j + 1, 0) - ctr) * wse[5 * W + k];
    } else {
        int k = j - 1; const int W = HSq - 2;
        float ctr = XF(f, j, Sq - 1);
        c0 = (XF(f, j - 1, Sq - 2) - ctr) * wnw[k];
        c1 = (XF(nf2, 0, Sq - 2 - k) - ctr) * wnw[W + k];
        c2 = (XF(f, j - 1, Sq - 1) - ctr) * wnw[2 * W + k]
           + (XF(nf2, 0, Sq - 1 - k) - ctr) * wnw[3 * W + k];
        c3 = (XF(f, j, Sq - 2) - ctr) * wnw[4 * W + k]
           + (XF(f, j + 1, Sq - 1) - ctr) * wnw[5 * W + k];
    }
}

// Inner scalar point
__device__ __forceinline__ void ipoint(
    const float* __restrict__ xp, const float* __restrict__ wi,
    int j, int i, float& c0, float& c1, float& c2, float& c3)
{
    const int WP = (HSq - 2) * (Sq - 2);
    int k = (j - 1) * (Sq - 2) + (i - 1);
    float ctr = xp[(size_t)j * Sq + i];
    c0 = (xp[(size_t)(j - 1) * Sq + i - 1] - ctr) * wi[k];
    c1 = (xp[(size_t)(j + 1) * Sq + i + 1] - ctr) * wi[WP + k];
    c2 = (xp[(size_t)(j - 1) * Sq + i] - ctr) * wi[2 * WP + k]
       + (xp[(size_t)j * Sq + i + 1] - ctr) * wi[3 * WP + k];
    c3 = (xp[(size_t)j * Sq + i - 1] - ctr) * wi[4 * WP + k]
       + (xp[(size_t)(j + 1) * Sq + i] - ctr) * wi[5 * WP + k];
}

__global__ void __launch_bounds__(128) fused_kernel(
    const float* __restrict__ x,
    const float* __restrict__ poles,
    const float* __restrict__ wi,
    const float* __restrict__ we,   const float* __restrict__ wcn,
    const float* __restrict__ wne,  const float* __restrict__ wnne,
    const float* __restrict__ wnw,  const float* __restrict__ wnww,
    const float* __restrict__ wwe,  const float* __restrict__ wsw,
    const float* __restrict__ wsse, const float* __restrict__ wse,
    const float* __restrict__ wcs,
    float* __restrict__ out)
{
    const size_t FP  = (size_t)HSq * Sq;     // one face plane
    const size_t CP5 = (size_t)NF * FP;      // comp stride in out

    int c  = 4 * (blockIdx.x * 128 + threadIdx.x);
    int ty = blockIdx.y;

    if (ty < HSq - 2) {
        // ===== interior rows j in [1, HS-2], loop over all 20 (b,f) =====
        int j = ty + 1;
        if (c >= 4 && c <= Sq - 8) {
            // pure inner, vectorized: 4 aligned columns [c, c+3]
            const int WP = (HSq - 2) * (Sq - 2);
            int kw = (j - 1) * (Sq - 2) + (c - 1);
            float w0[4], w1[4], w2[4], w3[4], w4[4], w5[4];
            #pragma unroll
            for (int l = 0; l < 4; l++) {
                w0[l] = wi[kw + l];
                w1[l] = wi[WP + kw + l];
                w2[l] = wi[2 * WP + kw + l];
                w3[l] = wi[3 * WP + kw + l];
                w4[l] = wi[4 * WP + kw + l];
                w5[l] = wi[5 * WP + kw + l];
            }
            #pragma unroll 1
            for (int b = 0; b < Bq; b++) {
                #pragma unroll 1
                for (int f = 0; f < NF; f++) {
                    const float* xp   = x + (size_t)(b * NF + f) * FP;
                    const float* rowm = xp + (size_t)(j - 1) * Sq;
                    const float* rowc = xp + (size_t)j * Sq;
                    const float* rowp = xp + (size_t)(j + 1) * Sq;
                    float4 rm = *(const float4*)(rowm + c);
                    float4 rc = *(const float4*)(rowc + c);
                    float4 rp = *(const float4*)(rowp + c);
                    float smm = rowm[c - 1];
                    float sm  = rowc[c - 1];
                    float sp  = rowc[c + 4];
                    float spp = rowp[c + 4];

                    float A[5]  = {smm, rm.x, rm.y, rm.z, rm.w};
                    float Bv[6] = {sm,  rc.x, rc.y, rc.z, rc.w, sp};
                    float Cv[5] = {rp.x, rp.y, rp.z, rp.w, spp};

                    float t0[4], t1[4], t2[4], t3[4];
                    #pragma unroll
                    for (int l = 0; l < 4; l++) {
                        float ctr = Bv[l + 1];
                        t0[l] = (A[l] - ctr) * w0[l];
                        t1[l] = (Cv[l + 1] - ctr) * w1[l];
                        t2[l] = (A[l + 1] - ctr) * w2[l] + (Bv[l + 2] - ctr) * w3[l];
                        t3[l] = (Bv[l] - ctr) * w4[l] + (Cv[l] - ctr) * w5[l];
                    }
                    size_t base = (size_t)(b * 20 + f) * FP + (size_t)j * Sq + c;
                    *(float4*)(out + base)           = make_float4(t0[0], t0[1], t0[2], t0[3]);
                    *(float4*)(out + base + CP5)     = make_float4(t1[0], t1[1], t1[2], t1[3]);
                    *(float4*)(out + base + 2 * CP5) = make_float4(t2[0], t2[1], t2[2], t2[3]);
                    *(float4*)(out + base + 3 * CP5) = make_float4(t3[0], t3[1], t3[2], t3[3]);
                }
            }
        } else {
            // edge chunk: c == 0 (contains col 0) or c == S-4 (contains col S-1)
            #pragma unroll 1
            for (int b = 0; b < Bq; b++) {
                const float* xb = x + (size_t)b * NF * FP;
                #pragma unroll 1
                for (int f = 0; f < NF; f++) {
                    int pf  = (f == 0) ? 4 : f - 1;
                    int nf2 = (f == 4) ? 0 : f + 1;
                    const float* xp = xb + (size_t)f * FP;
                    float t0[4], t1[4], t2[4], t3[4];
                    #pragma unroll
                    for (int l = 0; l < 4; l++) {
                        int i = c + l;
                        if (i == 0 || i == Sq - 1)
                            bpoint(xb, poles, we, wcn, wne, wnne, wnw, wnww,
                                   wwe, wsw, wsse, wse, wcs,
                                   b, f, pf, nf2, j, i, t0[l], t1[l], t2[l], t3[l]);
                        else
                            ipoint(xp, wi, j, i, t0[l], t1[l], t2[l], t3[l]);
                    }
                    size_t base = (size_t)(b * 20 + f) * FP + (size_t)j * Sq + c;
                    *(float4*)(out + base)           = make_float4(t0[0], t0[1], t0[2], t0[3]);
                    *(float4*)(out + base + CP5)     = make_float4(t1[0], t1[1], t1[2], t1[3]);
                    *(float4*)(out + base + 2 * CP5) = make_float4(t2[0], t2[1], t2[2], t2[3]);
                    *(float4*)(out + base + 3 * CP5) = make_float4(t3[0], t3[1], t3[2], t3[3]);
                }
            }
        }
    } else {
        // ===== boundary rows j=0 / j=HS-1: one block-row per (row, bf) =====
        int q   = ty - (HSq - 2);            // 0..39
        int row = (q < 20) ? 0 : (HSq - 1);
        int bf  = (q < 20) ? q : q - 20;
        int b = bf / NF, f = bf % NF;
        int pf  = (f == 0) ? 4 : f - 1;
        int nf2 = (f == 4) ? 0 : f + 1;
        const float* xb = x + (size_t)b * NF * FP;

        float t0[4], t1[4], t2[4], t3[4];
        #pragma unroll
        for (int l = 0; l < 4; l++) {
            bpoint(xb, poles, we, wcn, wne, wnne, wnw, wnww,
                   wwe, wsw, wsse, wse, wcs,
                   b, f, pf, nf2, row, c + l, t0[l], t1[l], t2[l], t3[l]);
        }
        size_t base = (size_t)(b * 20 + f) * FP + (size_t)row * Sq + c;
        *(float4*)(out + base)           = make_float4(t0[0], t0[1], t0[2], t0[3]);
        *(float4*)(out + base + CP5)     = make_float4(t1[0], t1[1], t1[2], t1[3]);
        *(float4*)(out + base + 2 * CP5) = make_float4(t2[0], t2[1], t2[2], t2[3]);
        *(float4*)(out + base + 3 * CP5) = make_float4(t3[0], t3[1], t3[2], t3[3]);
    }
}

extern "C" void kernel_launch(void* const* d_in, const int* in_sizes, int n_in,
                              void* d_out, int out_size)
{
    const float* x     = (const float*)d_in[0];
    const float* poles = (const float*)d_in[1];
    const float* wi    = (const float*)d_in[2];
    const float* we    = (const float*)d_in[3];
    const float* wcn   = (const float*)d_in[4];
    const float* wne   = (const float*)d_in[5];
    const float* wnne  = (const float*)d_in[6];
    const float* wnw   = (const float*)d_in[7];
    const float* wnww  = (const float*)d_in[8];
    const float* wwe   = (const float*)d_in[9];
    const float* wsw   = (const float*)d_in[10];
    const float* wsse  = (const float*)d_in[11];
    const float* wse   = (const float*)d_in[12];
    const float* wcs   = (const float*)d_in[13];
    float* out = (float*)d_out;

    // grid.y: 510 interior rows + 40 boundary-row blocks (2 rows x 20 bf)
    dim3 block(128, 1, 1);
    dim3 grid(Sq / (4 * 128), (HSq - 2) + 40, 1);
    fused_kernel<<<grid, block>>>(x, poles, wi, we, wcn, wne, wnne, wnw, wnww,
                                  wwe, wsw, wsse, wse, wcs, out);
}

// round 3
// speedup vs baseline: 1.2640x; 1.1717x over previous
#include <cuda_runtime.h>
#include <cuda_bf16.h>
#include <cstdint>

#define Bq 4
#define NF 5
#define HSq 512
#define Sq 1024

#define XF(ff,jj,ii) xb[((size_t)(ff)*HSq + (jj))*Sq + (ii)]

// Boundary point: ports the reference's 12 perimeter cases for one (j,i).
__device__ __forceinline__ void bpoint(
    const float* __restrict__ xb, const float* __restrict__ poles,
    const float* __restrict__ we,   const float* __restrict__ wcn,
    const float* __restrict__ wne,  const float* __restrict__ wnne,
    const float* __restrict__ wnw,  const float* __restrict__ wnww,
    const float* __restrict__ wwe,  const float* __restrict__ wsw,
    const float* __restrict__ wsse, const float* __restrict__ wse,
    const float* __restrict__ wcs,
    int b, int f, int pf, int nf2, int j, int i,
    float& c0, float& c1, float& c2, float& c3)
{
    if (j == 0) {
        float ctr = XF(f, 0, i);
        if (i == 0) {
            c0 = (XF(pf, HSq - 1, HSq - 1) - ctr) * wcs[0];
            c1 = (XF(f, 1, 1) - ctr) * wcs[1];
            c2 = (XF(pf, HSq - 1, HSq) - ctr) * wcs[2] + (XF(f, 0, 1) - ctr) * wcs[3];
            c3 = (XF(f, 1, 0) - ctr) * wcs[4];
        } else if (i <= HSq - 1) {
            int k = i - 1; const int W = HSq - 1;
            c0 = (XF(pf, HSq - 1, HSq + k) - ctr) * we[k];
            c1 = (XF(f, 1, i + 1) - ctr) * we[W + k];
            c2 = (XF(pf, HSq - 1, HSq + 1 + k) - ctr) * we[2 * W + k]
               + (XF(f, 0, i + 1) - ctr) * we[3 * W + k];
            c3 = (XF(f, 0, i - 1) - ctr) * we[4 * W + k]
               + (XF(f, 1, i) - ctr) * we[5 * W + k];
        } else if (i == HSq) {
            c0 = (XF(pf, HSq - 1, Sq - 1) - ctr) * wcn[0];
            c1 = (XF(f, 1, HSq + 1) - ctr) * wcn[1];
            c2 = (XF(f, 0, HSq + 1) - ctr) * wcn[2];
            c3 = (XF(f, 0, HSq - 1) - ctr) * wcn[3] + (XF(f, 1, HSq) - ctr) * wcn[4];
        } else if (i <= Sq - 2) {
            int k = i - (HSq + 1); const int W = HSq - 2;
            c0 = (XF(pf, HSq - 2 - k, Sq - 1) - ctr) * wne[k]
               + (XF(pf, HSq - 1 - k, Sq - 1) - ctr) * wne[W + k];
            c1 = (XF(f, 1, i + 1) - ctr) * wne[2 * W + k]
               + (XF(f, 1, i) - ctr) * wne[3 * W + k];
            c2 = (XF(f, 0, i + 1) - ctr) * wne[4 * W + k];
            c3 = (XF(f, 0, i - 1) - ctr) * wne[5 * W + k];
        } else {
            c0 = (XF(pf, 0, Sq - 1) - ctr) * wnne[0] + (XF(pf, 1, Sq - 1) - ctr) * wnne[1];
            c1 = (XF(nf2, 0, Sq - 1) - ctr) * wnne[2] + (XF(f, 1, Sq - 1) - ctr) * wnne[3];
            c2 = (poles[b * 2 + 1] - ctr) * wnne[4];
            c3 = (XF(f, 0, Sq - 2) - ctr) * wnne[5];
        }
    } else if (j == HSq - 1) {
        float ctr = XF(f, HSq - 1, i);
        if (i == 0) {
            c0 = (XF(pf, HSq - 1, 0) - ctr) * wsse[0];
            c1 = (XF(nf2, HSq - 1, 0) - ctr) * wsse[1];
            c2 = (XF(f, HSq - 2, 0) - ctr) * wsse[2] + (XF(f, HSq - 1, 1) - ctr) * wsse[3];
            c3 = (poles[b * 2 + 0] - ctr) * wsse[4];
        } else if (i <= HSq - 1) {
            int k = i - 1; const int W = HSq - 1;
            c0 = (XF(f, HSq - 2, i - 1) - ctr) * wsw[k];
            c1 = (XF(nf2, HSq - 2 - k, 0) - ctr) * wsw[W + k];
            c2 = (XF(f, HSq - 2, i) - ctr) * wsw[2 * W + k]
               + (XF(f, HSq - 1, i + 1) - ctr) * wsw[3 * W + k];
            c3 = (XF(f, HSq - 1, i - 1) - ctr) * wsw[4 * W + k]
               + (XF(nf2, HSq - 1 - k, 0) - ctr) * wsw[5 * W + k];
        } else if (i <= Sq - 2) {
            int k = i - HSq; const int W = HSq - 1;
            c0 = (XF(f, HSq - 2, i - 1) - ctr) * wwe[k];
            c1 = (XF(nf2, 0, 1 + k) - ctr) * wwe[W + k];
            c2 = (XF(f, HSq - 2, i) - ctr) * wwe[2 * W + k]
               + (XF(f, HSq - 1, i + 1) - ctr) * wwe[3 * W + k];
            c3 = (XF(f, HSq - 1, i - 1) - ctr) * wwe[4 * W + k]
               + (XF(nf2, 0, k) - ctr) * wwe[5 * W + k];
        } else {
            c0 = (XF(f, HSq - 2, Sq - 2) - ctr) * wnww[0];
            c1 = (XF(nf2, 0, HSq) - ctr) * wnww[1];
            c2 = (XF(f, HSq - 2, Sq - 1) - ctr) * wnww[2]
               + (XF(nf2, 0, HSq + 1) - ctr) * wnww[3];
            c3 = (XF(f, HSq - 1, Sq - 2) - ctr) * wnww[4]
               + (XF(nf2, 0, HSq - 1) - ctr) * wnww[5];
        }
    } else if (i == 0) {
        int k = j - 1; const int W = HSq - 2;
        float ctr = XF(f, j, 0);
        c0 = (XF(pf, HSq - 1, HSq - 1 - k) - ctr) * wse[k]
           + (XF(pf, HSq - 1, HSq - 2 - k) - ctr) * wse[W + k];
        c1 = (XF(f, j, 1) - ctr) * wse[2 * W + k]
           + (XF(f, j + 1, 1) - ctr) * wse[3 * W + k];
        c2 = (XF(f, j - 1, 0) - ctr) * wse[4 * W + k];
        c3 = (XF(f, j + 1, 0) - ctr) * wse[5 * W + k];
    } else {
        int k = j - 1; const int W = HSq - 2;
        float ctr = XF(f, j, Sq - 1);
        c0 = (XF(f, j - 1, Sq - 2) - ctr) * wnw[k];
        c1 = (XF(nf2, 0, Sq - 2 - k) - ctr) * wnw[W + k];
        c2 = (XF(f, j - 1, Sq - 1) - ctr) * wnw[2 * W + k]
           + (XF(nf2, 0, Sq - 1 - k) - ctr) * wnw[3 * W + k];
        c3 = (XF(f, j, Sq - 2) - ctr) * wnw[4 * W + k]
           + (XF(f, j + 1, Sq - 1) - ctr) * wnw[5 * W + k];
    }
}

// Inner scalar point
__device__ __forceinline__ void ipoint(
    const float* __restrict__ xp, const float* __restrict__ wi,
    int j, int i, float& c0, float& c1, float& c2, float& c3)
{
    const int WP = (HSq - 2) * (Sq - 2);
    int k = (j - 1) * (Sq - 2) + (i - 1);
    float ctr = xp[(size_t)j * Sq + i];
    c0 = (xp[(size_t)(j - 1) * Sq + i - 1] - ctr) * wi[k];
    c1 = (xp[(size_t)(j + 1) * Sq + i + 1] - ctr) * wi[WP + k];
    c2 = (xp[(size_t)(j - 1) * Sq + i] - ctr) * wi[2 * WP + k]
       + (xp[(size_t)j * Sq + i + 1] - ctr) * wi[3 * WP + k];
    c3 = (xp[(size_t)j * Sq + i - 1] - ctr) * wi[4 * WP + k]
       + (xp[(size_t)(j + 1) * Sq + i] - ctr) * wi[5 * WP + k];
}

__global__ void __launch_bounds__(128) fused_kernel(
    const float* __restrict__ x,
    const float* __restrict__ poles,
    const float* __restrict__ wi,
    const float* __restrict__ we,   const float* __restrict__ wcn,
    const float* __restrict__ wne,  const float* __restrict__ wnne,
    const float* __restrict__ wnw,  const float* __restrict__ wnww,
    const float* __restrict__ wwe,  const float* __restrict__ wsw,
    const float* __restrict__ wsse, const float* __restrict__ wse,
    const float* __restrict__ wcs,
    float* __restrict__ out)
{
    const size_t FP  = (size_t)HSq * Sq;     // one face plane
    const size_t CP5 = (size_t)NF * FP;      // comp stride in out

    int c  = 4 * (blockIdx.x * 128 + threadIdx.x);
    int ty = blockIdx.y;
    int f  = blockIdx.z;
    int pf  = (f == 0) ? 4 : f - 1;
    int nf2 = (f == 4) ? 0 : f + 1;

    if (ty < HSq - 2) {
        // ===== interior rows j in [1, HS-2]; f from grid, loop over b =====
        int j = ty + 1;
        if (c >= 4 && c <= Sq - 8) {
            // pure inner, vectorized: 4 aligned columns [c, c+3]
            const int WP = (HSq - 2) * (Sq - 2);
            int kw = (j - 1) * (Sq - 2) + (c - 1);
            float w0[4], w1[4], w2[4], w3[4], w4[4], w5[4];
            #pragma unroll
            for (int l = 0; l < 4; l++) {
                w0[l] = wi[kw + l];
                w1[l] = wi[WP + kw + l];
                w2[l] = wi[2 * WP + kw + l];
                w3[l] = wi[3 * WP + kw + l];
                w4[l] = wi[4 * WP + kw + l];
                w5[l] = wi[5 * WP + kw + l];
            }
            #pragma unroll 2
            for (int b = 0; b < Bq; b++) {
                const float* xp   = x + (size_t)(b * NF + f) * FP;
                const float* rowm = xp + (size_t)(j - 1) * Sq;
                const float* rowc = xp + (size_t)j * Sq;
                const float* rowp = xp + (size_t)(j + 1) * Sq;
                float4 rm = *(const float4*)(rowm + c);
                float4 rc = *(const float4*)(rowc + c);
                float4 rp = *(const float4*)(rowp + c);
                float smm = rowm[c - 1];
                float sm  = rowc[c - 1];
                float sp  = rowc[c + 4];
                float spp = rowp[c + 4];

                float A[5]  = {smm, rm.x, rm.y, rm.z, rm.w};
                float Bv[6] = {sm,  rc.x, rc.y, rc.z, rc.w, sp};
                float Cv[5] = {rp.x, rp.y, rp.z, rp.w, spp};

                float t0[4], t1[4], t2[4], t3[4];
                #pragma unroll
                for (int l = 0; l < 4; l++) {
                    float ctr = Bv[l + 1];
                    t0[l] = (A[l] - ctr) * w0[l];
                    t1[l] = (Cv[l + 1] - ctr) * w1[l];
                    t2[l] = (A[l + 1] - ctr) * w2[l] + (Bv[l + 2] - ctr) * w3[l];
                    t3[l] = (Bv[l] - ctr) * w4[l] + (Cv[l] - ctr) * w5[l];
                }
                size_t base = (size_t)(b * 20 + f) * FP + (size_t)j * Sq + c;
                *(float4*)(out + base)           = make_float4(t0[0], t0[1], t0[2], t0[3]);
                *(float4*)(out + base + CP5)     = make_float4(t1[0], t1[1], t1[2], t1[3]);
                *(float4*)(out + base + 2 * CP5) = make_float4(t2[0], t2[1], t2[2], t2[3]);
                *(float4*)(out + base + 3 * CP5) = make_float4(t3[0], t3[1], t3[2], t3[3]);
            }
        } else {
            // edge chunk: c == 0 (contains col 0) or c == S-4 (contains col S-1)
            #pragma unroll 1
            for (int b = 0; b < Bq; b++) {
                const float* xb = x + (size_t)b * NF * FP;
                const float* xp = xb + (size_t)f * FP;
                float t0[4], t1[4], t2[4], t3[4];
                #pragma unroll
                for (int l = 0; l < 4; l++) {
                    int i = c + l;
                    if (i == 0 || i == Sq - 1)
                        bpoint(xb, poles, we, wcn, wne, wnne, wnw, wnww,
                               wwe, wsw, wsse, wse, wcs,
                               b, f, pf, nf2, j, i, t0[l], t1[l], t2[l], t3[l]);
                    else
                        ipoint(xp, wi, j, i, t0[l], t1[l], t2[l], t3[l]);
                }
                size_t base = (size_t)(b * 20 + f) * FP + (size_t)j * Sq + c;
                *(float4*)(out + base)           = make_float4(t0[0], t0[1], t0[2], t0[3]);
                *(float4*)(out + base + CP5)     = make_float4(t1[0], t1[1], t1[2], t1[3]);
                *(float4*)(out + base + 2 * CP5) = make_float4(t2[0], t2[1], t2[2], t2[3]);
                *(float4*)(out + base + 3 * CP5) = make_float4(t3[0], t3[1], t3[2], t3[3]);
            }
        }
    } else {
        // ===== boundary rows j=0 / j=HS-1: one block per (row, b) x f-grid =====
        int q   = ty - (HSq - 2);            // 0..(2*Bq-1)
        int row = (q < Bq) ? 0 : (HSq - 1);
        int b   = (q < Bq) ? q : q - Bq;
        const float* xb = x + (size_t)b * NF * FP;

        float t0[4], t1[4], t2[4], t3[4];
        #pragma unroll
        for (int l = 0; l < 4; l++) {
            bpoint(xb, poles, we, wcn, wne, wnne, wnw, wnww,
                   wwe, wsw, wsse, wse, wcs,
                   b, f, pf, nf2, row, c + l, t0[l], t1[l], t2[l], t3[l]);
        }
        size_t base = (size_t)(b * 20 + f) * FP + (size_t)row * Sq + c;
        *(float4*)(out + base)           = make_float4(t0[0], t0[1], t0[2], t0[3]);
        *(float4*)(out + base + CP5)     = make_float4(t1[0], t1[1], t1[2], t1[3]);
        *(float4*)(out + base + 2 * CP5) = make_float4(t2[0], t2[1], t2[2], t2[3]);
        *(float4*)(out + base + 3 * CP5) = make_float4(t3[0], t3[1], t3[2], t3[3]);
    }
}

extern "C" void kernel_launch(void* const* d_in, const int* in_sizes, int n_in,
                              void* d_out, int out_size)
{
    const float* x     = (const float*)d_in[0];
    const float* poles = (const float*)d_in[1];
    const float* wi    = (const float*)d_in[2];
    const float* we    = (const float*)d_in[3];
    const float* wcn   = (const float*)d_in[4];
    const float* wne   = (const float*)d_in[5];
    const float* wnne  = (const float*)d_in[6];
    const float* wnw   = (const float*)d_in[7];
    const float* wnww  = (const float*)d_in[8];
    const float* wwe   = (const float*)d_in[9];
    const float* wsw   = (const float*)d_in[10];
    const float* wsse  = (const float*)d_in[11];
    const float* wse   = (const float*)d_in[12];
    const float* wcs   = (const float*)d_in[13];
    float* out = (float*)d_out;

    // grid.y: 510 interior rows + 2*Bq boundary-row blocks; grid.z: faces
    dim3 block(128, 1, 1);
    dim3 grid(Sq / (4 * 128), (HSq - 2) + 2 * Bq, NF);
    fused_kernel<<<grid, block>>>(x, poles, wi, we, wcn, wne, wnne, wnw, wnww,
                                  wwe, wsw, wsse, wse, wcs, out);
}